// round 9
// baseline (speedup 1.0000x reference)
#include <cuda_runtime.h>
#include <cstddef>

// pred_raw[b, 4h+i, 4w+j] = y[b, C[k], 4h+RO[k], 4w+CO[k]], k = 4*i+j.
// k=15 duplicates k=3 -> 15 unique y loads / 16 px. Tables indexed with
// compile-time k only (full unroll) -> immediate offsets, no local memory.
// New in R9: register-free L2 prefetch of BOTH tiles' addresses up front to
// decouple MLP from register allocation (tests the latency-exposure theory).

#define NB      1024           // 8 batches * 128 tile-pairs
#define N_TOTAL 8388608.0f

__device__ float        g_partials[NB];
__device__ unsigned int g_done = 0;

__device__ __forceinline__ void pf_l2(const float* p) {
    asm volatile("prefetch.global.L2 [%0];" :: "l"(p));
}

__global__ void __launch_bounds__(256)
loss_fused(const float* __restrict__ x, const float* __restrict__ y,
           float* __restrict__ out)
{
    const int tid  = threadIdx.x;
    const int lane = tid & 31;
    const int warp = tid >> 5;
    const int g    = blockIdx.x;
    const int b    = g >> 7;
    const int hh   = g & 127;          // tile-pair: tiles h = 2*hh, 2*hh+1

    const int kC[16]  = {0,3,1,4, 6,9,7,10, 1,4,8,10, 2,5,9,4};
    const int kRO[16] = {0,0,0,0, 1,1,1,1,  2,2,3,3,  2,2,3,0};
    const int kCO[16] = {0,1,2,3, 0,1,2,3,  0,1,0,1,  2,3,2,3};

    // ---- Phase 0: register-free deep-MLP L2 prefetch of all 38 lines ----
    #pragma unroll
    for (int u = 0; u < 2; u++) {
        const int h = (hh << 1) + u;
        const size_t xbase = ((((size_t)b << 10) + (h << 2)) << 10) + (tid << 2);
        #pragma unroll
        for (int i = 0; i < 4; i++)
            pf_l2(x + xbase + ((size_t)i << 10));
        const size_t ybase = (((size_t)(b * 12)) << 20)
                           + (((size_t)(h << 2)) << 10) + (tid << 2);
        #pragma unroll
        for (int k = 0; k < 15; k++)
            pf_l2(y + ybase + ((size_t)kC[k] << 20) + ((size_t)kRO[k] << 10) + kCO[k]);
    }

    // ---- main body (R5 structure) ----
    float s = 0.0f;
    #pragma unroll
    for (int u = 0; u < 2; u++) {
        const int h = (hh << 1) + u;

        float xs[16];
        {
            const size_t xbase = ((((size_t)b << 10) + (h << 2)) << 10) + (tid << 2);
            #pragma unroll
            for (int i = 0; i < 4; i++) {
                float4 v = *reinterpret_cast<const float4*>(x + xbase + ((size_t)i << 10));
                xs[4*i+0] = v.x; xs[4*i+1] = v.y; xs[4*i+2] = v.z; xs[4*i+3] = v.w;
            }
        }

        float yv[16];
        const size_t ybase = (((size_t)(b * 12)) << 20)
                           + (((size_t)(h << 2)) << 10) + (tid << 2);
        #pragma unroll
        for (int k = 0; k < 15; k++)
            yv[k] = y[ybase + ((size_t)kC[k] << 20) + ((size_t)kRO[k] << 10) + kCO[k]];
        yv[15] = yv[3];

        #pragma unroll
        for (int k = 0; k < 16; k++)
            s += fabsf(yv[k] - xs[k]);
    }

    // ---- deterministic block reduction ----
    #pragma unroll
    for (int m = 16; m > 0; m >>= 1)
        s += __shfl_xor_sync(0xFFFFFFFFu, s, m);

    __shared__ float sm[8];
    __shared__ bool  s_last;
    if (lane == 0) sm[warp] = s;
    __syncthreads();
    if (tid == 0) {
        float v = 0.0f;
        #pragma unroll
        for (int w = 0; w < 8; w++) v += sm[w];
        g_partials[g] = v;
        __threadfence();
        unsigned int prev = atomicAdd(&g_done, 1u);
        s_last = (prev == NB - 1);
    }
    __syncthreads();

    // ---- last block: fixed-order final sum (deterministic) ----
    if (s_last) {
        float t = 0.0f;
        #pragma unroll 4
        for (int idx = tid; idx < NB; idx += 256)
            t += g_partials[idx];
        #pragma unroll
        for (int m = 16; m > 0; m >>= 1)
            t += __shfl_xor_sync(0xFFFFFFFFu, t, m);
        if (lane == 0) sm[warp] = t;
        __syncthreads();
        if (tid == 0) {
            float v = 0.0f;
            #pragma unroll
            for (int w = 0; w < 8; w++) v += sm[w];
            out[0] = v * (1.0f / N_TOTAL);
            g_done = 0;                  // reset for next graph replay
        }
    }
}

extern "C" void kernel_launch(void* const* d_in, const int* in_sizes, int n_in,
                              void* d_out, int out_size) {
    const float* x;
    const float* y;
    if (in_sizes[0] == 8 * 1024 * 1024) {
        x = (const float*)d_in[0];
        y = (const float*)d_in[1];
    } else {
        x = (const float*)d_in[1];
        y = (const float*)d_in[0];
    }
    loss_fused<<<NB, 256>>>(x, y, (float*)d_out);
}

// round 10
// speedup vs baseline: 1.1133x; 1.1133x over previous
#include <cuda_runtime.h>
#include <cstddef>

// pred_raw[b, 4h+i, 4w+j] = y[b, C[k], 4h+RO[k], 4w+CO[k]], k = 4*i+j.
// k=15 duplicates k=3 -> 15 unique y loads / 16 px. Tables indexed with
// compile-time k only (full unroll) -> immediate offsets, no local memory.
// Best-known config (R5) + cheaper release/acquire epilogue (no L1 flush).

#define NB      1024           // 8 batches * 128 tile-pairs
#define N_TOTAL 8388608.0f

__device__ float        g_partials[NB];
__device__ unsigned int g_done = 0;

__global__ void __launch_bounds__(256)
loss_fused(const float* __restrict__ x, const float* __restrict__ y,
           float* __restrict__ out)
{
    const int tid  = threadIdx.x;
    const int lane = tid & 31;
    const int warp = tid >> 5;
    const int g    = blockIdx.x;
    const int b    = g >> 7;
    const int hh   = g & 127;          // tile-pair: tiles h = 2*hh, 2*hh+1

    float s = 0.0f;

    #pragma unroll
    for (int u = 0; u < 2; u++) {
        const int h = (hh << 1) + u;

        // x: 4 coalesced float4 rows of this 4x1024 tile
        float xs[16];
        {
            const size_t xbase = ((((size_t)b << 10) + (h << 2)) << 10) + (tid << 2);
            #pragma unroll
            for (int i = 0; i < 4; i++) {
                float4 v = *reinterpret_cast<const float4*>(x + xbase + ((size_t)i << 10));
                xs[4*i+0] = v.x; xs[4*i+1] = v.y; xs[4*i+2] = v.z; xs[4*i+3] = v.w;
            }
        }

        // y: 15 unique scalar loads, constant-folded immediate offsets
        const int kC[16]  = {0,3,1,4, 6,9,7,10, 1,4,8,10, 2,5,9,4};
        const int kRO[16] = {0,0,0,0, 1,1,1,1,  2,2,3,3,  2,2,3,0};
        const int kCO[16] = {0,1,2,3, 0,1,2,3,  0,1,0,1,  2,3,2,3};

        float yv[16];
        const size_t ybase = (((size_t)(b * 12)) << 20)
                           + (((size_t)(h << 2)) << 10) + (tid << 2);
        #pragma unroll
        for (int k = 0; k < 15; k++)
            yv[k] = y[ybase + ((size_t)kC[k] << 20) + ((size_t)kRO[k] << 10) + kCO[k]];
        yv[15] = yv[3];

        #pragma unroll
        for (int k = 0; k < 16; k++)
            s += fabsf(yv[k] - xs[k]);
    }

    // ---- deterministic block reduction ----
    #pragma unroll
    for (int m = 16; m > 0; m >>= 1)
        s += __shfl_xor_sync(0xFFFFFFFFu, s, m);

    __shared__ float sm[8];
    __shared__ bool  s_last;
    if (lane == 0) sm[warp] = s;
    __syncthreads();
    if (tid == 0) {
        float v = 0.0f;
        #pragma unroll
        for (int w = 0; w < 8; w++) v += sm[w];
        g_partials[g] = v;
        // release-increment: orders the partial store without an L1 flush;
        // acquire side covers the last block's partial reads.
        unsigned int prev;
        asm volatile("atom.acq_rel.gpu.global.add.u32 %0, [%1], %2;"
                     : "=r"(prev) : "l"(&g_done), "r"(1u) : "memory");
        s_last = (prev == NB - 1);
    }
    __syncthreads();

    // ---- last block: fixed-order final sum (deterministic) ----
    if (s_last) {
        float t = 0.0f;
        #pragma unroll 4
        for (int idx = tid; idx < NB; idx += 256)
            t += __ldcg(&g_partials[idx]);      // L2 read (bypass L1)
        #pragma unroll
        for (int m = 16; m > 0; m >>= 1)
            t += __shfl_xor_sync(0xFFFFFFFFu, t, m);
        if (lane == 0) sm[warp] = t;
        __syncthreads();
        if (tid == 0) {
            float v = 0.0f;
            #pragma unroll
            for (int w = 0; w < 8; w++) v += sm[w];
            out[0] = v * (1.0f / N_TOTAL);
            g_done = 0;                  // reset for next graph replay
        }
    }
}

extern "C" void kernel_launch(void* const* d_in, const int* in_sizes, int n_in,
                              void* d_out, int out_size) {
    const float* x;
    const float* y;
    if (in_sizes[0] == 8 * 1024 * 1024) {
        x = (const float*)d_in[0];
        y = (const float*)d_in[1];
    } else {
        x = (const float*)d_in[1];
        y = (const float*)d_in[0];
    }
    loss_fused<<<NB, 256>>>(x, y, (float*)d_out);
}

// round 11
// speedup vs baseline: 1.1225x; 1.0083x over previous
#include <cuda_runtime.h>
#include <cstddef>

// pred_raw[b, 4h+i, 4w+j] = y[b, C[k], 4h+RO[k], 4w+CO[k]], k = 4*i+j.
// k=15 duplicates k=3 exactly -> reuse in-register (15 unique y loads / 16 px).
// Tables indexed only with compile-time-constant k (full unroll) -> immediate
// address offsets, no local memory.
//
// FINAL: R5 configuration — empirically fastest of 10 structurally distinct
// variants (29.25 us). Traffic is at the provable 152 MB floor; achieved
// 5.4 TB/s is the measured platform ceiling for this access mix (invariant
// across scheduling, MLP depth, stream count, prefetch, and fence variants).

#define NB      1024           // 8 batches * 128 tile-pairs
#define N_TOTAL 8388608.0f

__device__ float        g_partials[NB];
__device__ unsigned int g_done = 0;

__global__ void __launch_bounds__(256)
loss_fused(const float* __restrict__ x, const float* __restrict__ y,
           float* __restrict__ out)
{
    const int tid  = threadIdx.x;
    const int lane = tid & 31;
    const int warp = tid >> 5;
    const int g    = blockIdx.x;
    const int b    = g >> 7;
    const int hh   = g & 127;          // tile-pair: tiles h = 2*hh, 2*hh+1

    float s = 0.0f;

    #pragma unroll
    for (int u = 0; u < 2; u++) {
        const int h = (hh << 1) + u;

        // x: 4 coalesced float4 rows of this 4x1024 tile
        float xs[16];
        {
            const size_t xbase = ((((size_t)b << 10) + (h << 2)) << 10) + (tid << 2);
            #pragma unroll
            for (int i = 0; i < 4; i++) {
                float4 v = *reinterpret_cast<const float4*>(x + xbase + ((size_t)i << 10));
                xs[4*i+0] = v.x; xs[4*i+1] = v.y; xs[4*i+2] = v.z; xs[4*i+3] = v.w;
            }
        }

        // y: 15 unique scalar loads, constant-folded immediate offsets
        const int kC[16]  = {0,3,1,4, 6,9,7,10, 1,4,8,10, 2,5,9,4};
        const int kRO[16] = {0,0,0,0, 1,1,1,1,  2,2,3,3,  2,2,3,0};
        const int kCO[16] = {0,1,2,3, 0,1,2,3,  0,1,0,1,  2,3,2,3};

        float yv[16];
        const size_t ybase = (((size_t)(b * 12)) << 20)
                           + (((size_t)(h << 2)) << 10) + (tid << 2);
        #pragma unroll
        for (int k = 0; k < 15; k++)
            yv[k] = y[ybase + ((size_t)kC[k] << 20) + ((size_t)kRO[k] << 10) + kCO[k]];
        yv[15] = yv[3];

        #pragma unroll
        for (int k = 0; k < 16; k++)
            s += fabsf(yv[k] - xs[k]);
    }

    // ---- deterministic block reduction ----
    #pragma unroll
    for (int m = 16; m > 0; m >>= 1)
        s += __shfl_xor_sync(0xFFFFFFFFu, s, m);

    __shared__ float sm[8];
    __shared__ bool  s_last;
    if (lane == 0) sm[warp] = s;
    __syncthreads();
    if (tid == 0) {
        float v = 0.0f;
        #pragma unroll
        for (int w = 0; w < 8; w++) v += sm[w];
        g_partials[g] = v;
        __threadfence();
        unsigned int prev = atomicAdd(&g_done, 1u);
        s_last = (prev == NB - 1);
    }
    __syncthreads();

    // ---- last block: fixed-order final sum (deterministic) ----
    if (s_last) {
        float t = 0.0f;
        #pragma unroll 4
        for (int idx = tid; idx < NB; idx += 256)
            t += g_partials[idx];
        #pragma unroll
        for (int m = 16; m > 0; m >>= 1)
            t += __shfl_xor_sync(0xFFFFFFFFu, t, m);
        if (lane == 0) sm[warp] = t;
        __syncthreads();
        if (tid == 0) {
            float v = 0.0f;
            #pragma unroll
            for (int w = 0; w < 8; w++) v += sm[w];
            out[0] = v * (1.0f / N_TOTAL);
            g_done = 0;                  // reset for next graph replay
        }
    }
}

extern "C" void kernel_launch(void* const* d_in, const int* in_sizes, int n_in,
                              void* d_out, int out_size) {
    const float* x;
    const float* y;
    if (in_sizes[0] == 8 * 1024 * 1024) {
        x = (const float*)d_in[0];
        y = (const float*)d_in[1];
    } else {
        x = (const float*)d_in[1];
        y = (const float*)d_in[0];
    }
    loss_fused<<<NB, 256>>>(x, y, (float*)d_out);
}

// round 12
// speedup vs baseline: 1.1237x; 1.0010x over previous
#include <cuda_runtime.h>
#include <cstddef>

// pred_raw[b, 4h+i, 4w+j] = y[b, C[k], 4h+RO[k], 4w+CO[k]], k = 4*i+j.
// k=15 duplicates k=3 exactly -> reuse in-register (15 unique y loads / 16 px).
// Tables indexed only with compile-time-constant k (full unroll) -> immediate
// address offsets, no local memory.
//
// FINAL (converged): best-measured configuration over 11 structurally distinct
// variants (29.25 us best sample; class noise band +/-1 us). DRAM traffic is at
// the provable 152 MB floor; achieved ~5.4 TB/s is the platform ceiling for
// this 16-stream read mix (invariant across scheduling, MLP depth, stream
// count, prefetch, and fence variants). 152 MB / 5.5 TB/s = 28 us attainable
// roofline; this kernel sits within 5% of it.

#define NB      1024           // 8 batches * 128 tile-pairs
#define N_TOTAL 8388608.0f

__device__ float        g_partials[NB];
__device__ unsigned int g_done = 0;

__global__ void __launch_bounds__(256)
loss_fused(const float* __restrict__ x, const float* __restrict__ y,
           float* __restrict__ out)
{
    const int tid  = threadIdx.x;
    const int lane = tid & 31;
    const int warp = tid >> 5;
    const int g    = blockIdx.x;
    const int b    = g >> 7;
    const int hh   = g & 127;          // tile-pair: tiles h = 2*hh, 2*hh+1

    float s = 0.0f;

    #pragma unroll
    for (int u = 0; u < 2; u++) {
        const int h = (hh << 1) + u;

        // x: 4 coalesced float4 rows of this 4x1024 tile
        float xs[16];
        {
            const size_t xbase = ((((size_t)b << 10) + (h << 2)) << 10) + (tid << 2);
            #pragma unroll
            for (int i = 0; i < 4; i++) {
                float4 v = *reinterpret_cast<const float4*>(x + xbase + ((size_t)i << 10));
                xs[4*i+0] = v.x; xs[4*i+1] = v.y; xs[4*i+2] = v.z; xs[4*i+3] = v.w;
            }
        }

        // y: 15 unique scalar loads, constant-folded immediate offsets
        const int kC[16]  = {0,3,1,4, 6,9,7,10, 1,4,8,10, 2,5,9,4};
        const int kRO[16] = {0,0,0,0, 1,1,1,1,  2,2,3,3,  2,2,3,0};
        const int kCO[16] = {0,1,2,3, 0,1,2,3,  0,1,0,1,  2,3,2,3};

        float yv[16];
        const size_t ybase = (((size_t)(b * 12)) << 20)
                           + (((size_t)(h << 2)) << 10) + (tid << 2);
        #pragma unroll
        for (int k = 0; k < 15; k++)
            yv[k] = y[ybase + ((size_t)kC[k] << 20) + ((size_t)kRO[k] << 10) + kCO[k]];
        yv[15] = yv[3];

        #pragma unroll
        for (int k = 0; k < 16; k++)
            s += fabsf(yv[k] - xs[k]);
    }

    // ---- deterministic block reduction ----
    #pragma unroll
    for (int m = 16; m > 0; m >>= 1)
        s += __shfl_xor_sync(0xFFFFFFFFu, s, m);

    __shared__ float sm[8];
    __shared__ bool  s_last;
    if (lane == 0) sm[warp] = s;
    __syncthreads();
    if (tid == 0) {
        float v = 0.0f;
        #pragma unroll
        for (int w = 0; w < 8; w++) v += sm[w];
        g_partials[g] = v;
        __threadfence();
        unsigned int prev = atomicAdd(&g_done, 1u);
        s_last = (prev == NB - 1);
    }
    __syncthreads();

    // ---- last block: fixed-order final sum (deterministic) ----
    if (s_last) {
        float t = 0.0f;
        #pragma unroll 4
        for (int idx = tid; idx < NB; idx += 256)
            t += g_partials[idx];
        #pragma unroll
        for (int m = 16; m > 0; m >>= 1)
            t += __shfl_xor_sync(0xFFFFFFFFu, t, m);
        if (lane == 0) sm[warp] = t;
        __syncthreads();
        if (tid == 0) {
            float v = 0.0f;
            #pragma unroll
            for (int w = 0; w < 8; w++) v += sm[w];
            out[0] = v * (1.0f / N_TOTAL);
            g_done = 0;                  // reset for next graph replay
        }
    }
}

extern "C" void kernel_launch(void* const* d_in, const int* in_sizes, int n_in,
                              void* d_out, int out_size) {
    const float* x;
    const float* y;
    if (in_sizes[0] == 8 * 1024 * 1024) {
        x = (const float*)d_in[0];
        y = (const float*)d_in[1];
    } else {
        x = (const float*)d_in[1];
        y = (const float*)d_in[0];
    }
    loss_fused<<<NB, 256>>>(x, y, (float*)d_out);
}